// round 5
// baseline (speedup 1.0000x reference)
#include <cuda_runtime.h>
#include <cstdint>

#define BB 64
#define CC 4096
#define IND 512
#define OO 16
#define TI 8                  // i-tile
#define NTILES (IND / TI)     // 64
#define NCAP 2                // capsules per CTA (one warp)
#define NTH 32

// x smem layout per capsule: 16 groups of (4 rows x 8 words) + 4 pad = 36 words.
// Conflict-free for staging (16B writes) and compute (LDS.128 reads).
#define XGRP 36
#define XCAP (16 * XGRP)      // 576 words per capsule

__device__ __forceinline__ int xbase(int r) {   // word offset of x row r
    return (r >> 2) * XGRP + (r & 3) * 8;
}

// ---- packed f32x2 helpers ----
__device__ __forceinline__ uint64_t pack_dup(float x) {
    uint64_t r;
    asm("mov.b64 %0, {%1, %1};" : "=l"(r) : "f"(x));
    return r;
}
__device__ __forceinline__ void fma2(uint64_t& d, uint64_t a, uint64_t b) {
    asm("fma.rn.f32x2 %0, %1, %2, %0;" : "+l"(d) : "l"(a), "l"(b));
}
__device__ __forceinline__ void unpack2(uint64_t v, float& lo, float& hi) {
    asm("mov.b64 {%0, %1}, %2;" : "=f"(lo), "=f"(hi) : "l"(v));
}

// ---- cp.async 16B ----
__device__ __forceinline__ void cp16(void* dst_smem, const void* src) {
    uint32_t d = (uint32_t)__cvta_generic_to_shared(dst_smem);
    asm volatile("cp.async.ca.shared.global [%0], [%1], 16;"
                 :: "r"(d), "l"(src) : "memory");
}
__device__ __forceinline__ void cp_commit() {
    asm volatile("cp.async.commit_group;" ::: "memory");
}
__device__ __forceinline__ void cp_wait1() {
    asm volatile("cp.async.wait_group 1;" ::: "memory");
}
__device__ __forceinline__ void cp_wait0() {
    asm volatile("cp.async.wait_group 0;" ::: "memory");
}

__global__ __launch_bounds__(NTH, 14)
void primarycaps_kernel(const float* __restrict__ x,
                        const float* __restrict__ W,
                        const float* __restrict__ bias,
                        float* __restrict__ out)
{
    __shared__ float sX[2][NCAP * XCAP];      // 2 x 4608 B
    __shared__ float sW[2][NCAP * TI * OO];   // 2 x 1024 B

    const int c0  = blockIdx.x * NCAP;
    const int t   = threadIdx.x;
    const int tb  = t & 7;           // compute: b-group, owns b = tb + 8k
    const int to  = (t >> 3) & 1;    // compute: o-half
    const int cap = t >> 4;          // capsule within warp

    // ---- staging maps ----
    const int xch = t & 1;           // x: 16B chunk within 32B row
    const int xr0 = (t >> 1) & 7;    // x: row base (rows xr0 + 8k)
    const int wch = t & 3;           // W: 16B chunk within 64B row
    const int wi0 = (t >> 2) & 3;    // W: i base (i = wi0 + 4m)

    const float* xg0 = x + ((size_t)xr0 * CC + c0 + cap) * IND + xch * 4;
    const float* wg0 = W + ((size_t)(c0 + cap) * IND + wi0) * OO + wch * 4;

    // ---- accumulators: 8 b-rows x 4 o-pairs (packed f32x2) ----
    uint64_t acc[8][4];
    #pragma unroll
    for (int k = 0; k < 8; ++k)
        #pragma unroll
        for (int j = 0; j < 4; ++j)
            acc[k][j] = 0ULL;

    // ---- stage tile 0 ----
    {
        float* dx = &sX[0][cap * XCAP];
        #pragma unroll
        for (int k = 0; k < 8; ++k)
            cp16(&dx[xbase(xr0 + 8 * k) + xch * 4],
                 xg0 + (size_t)(8 * k) * CC * IND);
        float* dw = &sW[0][cap * TI * OO];
        #pragma unroll
        for (int m = 0; m < 2; ++m)
            cp16(&dw[(wi0 + 4 * m) * OO + wch * 4],
                 wg0 + (size_t)(4 * m) * OO);
        cp_commit();
    }

    for (int j = 0; j < NTILES; ++j) {
        // issue tile j+1 into the other buffer, then wait for tile j
        if (j + 1 < NTILES) {
            const int nb = (j + 1) & 1;
            const float* xg = xg0 + (size_t)(j + 1) * TI;
            float* dx = &sX[nb][cap * XCAP];
            #pragma unroll
            for (int k = 0; k < 8; ++k)
                cp16(&dx[xbase(xr0 + 8 * k) + xch * 4],
                     xg + (size_t)(8 * k) * CC * IND);
            const float* wg = wg0 + (size_t)(j + 1) * TI * OO;
            float* dw = &sW[nb][cap * TI * OO];
            #pragma unroll
            for (int m = 0; m < 2; ++m)
                cp16(&dw[(wi0 + 4 * m) * OO + wch * 4],
                     wg + (size_t)(4 * m) * OO);
            cp_commit();
            cp_wait1();          // tile j landed; j+1 in flight
        } else {
            cp_wait0();
        }
        __syncwarp();

        // ---- compute tile j ----
        const float* __restrict__ xb = &sX[j & 1][cap * XCAP];
        const float* __restrict__ wb = &sW[j & 1][cap * TI * OO];

        #pragma unroll
        for (int q = 0; q < 2; ++q) {          // two 4-i blocks
            float4 xv[8];
            #pragma unroll
            for (int k = 0; k < 8; ++k)
                xv[k] = *(const float4*)&xb[xbase(tb + 8 * k) + q * 4];

            #pragma unroll
            for (int r = 0; r < 4; ++r) {
                const int i = q * 4 + r;
                const ulonglong2 wA =
                    *(const ulonglong2*)&wb[i * OO + to * 8];
                const ulonglong2 wB =
                    *(const ulonglong2*)&wb[i * OO + to * 8 + 4];

                #pragma unroll
                for (int k = 0; k < 8; ++k) {
                    const float xs = (r == 0) ? xv[k].x :
                                     (r == 1) ? xv[k].y :
                                     (r == 2) ? xv[k].z : xv[k].w;
                    const uint64_t xd = pack_dup(xs);
                    fma2(acc[k][0], xd, wA.x);
                    fma2(acc[k][1], xd, wA.y);
                    fma2(acc[k][2], xd, wB.x);
                    fma2(acc[k][3], xd, wB.y);
                }
            }
        }
        __syncwarp();   // reads of buffer j done before it is refilled (j+2)
    }

    // ---- epilogue ----
    const int c  = c0 + cap;
    const int o0 = to * 8;
    const float4* bias4 = (const float4*)(bias + (size_t)c * OO + o0);
    const float4 bz0 = bias4[0];
    const float4 bz1 = bias4[1];

    #pragma unroll
    for (int k = 0; k < 8; ++k) {
        float v0, v1, v2, v3, v4, v5, v6, v7;
        unpack2(acc[k][0], v0, v1);
        unpack2(acc[k][1], v2, v3);
        unpack2(acc[k][2], v4, v5);
        unpack2(acc[k][3], v6, v7);

        float4 lo = make_float4(v0 + bz0.x, v1 + bz0.y, v2 + bz0.z, v3 + bz0.w);
        float4 hi = make_float4(v4 + bz1.x, v5 + bz1.y, v6 + bz1.z, v7 + bz1.w);

        const int b = tb + 8 * k;
        float* op = out + ((size_t)b * CC + c) * OO + o0;
        *(float4*)(op)     = lo;
        *(float4*)(op + 4) = hi;
    }
}

extern "C" void kernel_launch(void* const* d_in, const int* in_sizes, int n_in,
                              void* d_out, int out_size)
{
    (void)in_sizes; (void)n_in; (void)out_size;
    const float* x    = (const float*)d_in[0];
    const float* W    = (const float*)d_in[1];
    const float* bias = (const float*)d_in[2];
    float*       out  = (float*)d_out;

    primarycaps_kernel<<<CC / NCAP, NTH>>>(x, W, bias, out);
}

// round 6
// speedup vs baseline: 1.2038x; 1.2038x over previous
#include <cuda_runtime.h>
#include <cstdint>

#define BB 64
#define CC 4096
#define IND 512
#define OO 16
#define TI 8                  // i-tile
#define NTILES (IND / TI)     // 64
#define NCAP 2                // capsules per CTA (one warp)
#define NTH 32
#define PIPE 4                // cp.async pipeline depth

// x smem layout per capsule: 16 groups of (4 rows x 8 words) + 4 pad = 36 words.
#define XGRP 36
#define XCAP (16 * XGRP)      // 576 words per capsule

__device__ __forceinline__ int xbase(int r) {   // word offset of x row r
    return (r >> 2) * XGRP + (r & 3) * 8;
}

// ---- packed f32x2 helpers ----
__device__ __forceinline__ uint64_t pack_dup(float x) {
    uint64_t r;
    asm("mov.b64 %0, {%1, %1};" : "=l"(r) : "f"(x));
    return r;
}
__device__ __forceinline__ void fma2(uint64_t& d, uint64_t a, uint64_t b) {
    asm("fma.rn.f32x2 %0, %1, %2, %0;" : "+l"(d) : "l"(a), "l"(b));
}
__device__ __forceinline__ void unpack2(uint64_t v, float& lo, float& hi) {
    asm("mov.b64 {%0, %1}, %2;" : "=f"(lo), "=f"(hi) : "l"(v));
}

// ---- cp.async 16B, L1-bypass ----
__device__ __forceinline__ void cp16(void* dst_smem, const void* src) {
    uint32_t d = (uint32_t)__cvta_generic_to_shared(dst_smem);
    asm volatile("cp.async.cg.shared.global [%0], [%1], 16;"
                 :: "r"(d), "l"(src) : "memory");
}
__device__ __forceinline__ void cp_commit() {
    asm volatile("cp.async.commit_group;" ::: "memory");
}
__device__ __forceinline__ void cp_wait2() {
    asm volatile("cp.async.wait_group 2;" ::: "memory");
}
__device__ __forceinline__ void cp_wait1() {
    asm volatile("cp.async.wait_group 1;" ::: "memory");
}
__device__ __forceinline__ void cp_wait0() {
    asm volatile("cp.async.wait_group 0;" ::: "memory");
}

__global__ __launch_bounds__(NTH, 10)
void primarycaps_kernel(const float* __restrict__ x,
                        const float* __restrict__ W,
                        const float* __restrict__ bias,
                        float* __restrict__ out)
{
    __shared__ float sX[PIPE][NCAP * XCAP];      // 4 x 4608 B
    __shared__ float sW[PIPE][NCAP * TI * OO];   // 4 x 1024 B

    const int c0  = blockIdx.x * NCAP;
    const int t   = threadIdx.x;
    const int tb  = t & 7;           // compute: b-group, owns b = tb + 8k
    const int to  = (t >> 3) & 1;    // compute: o-half
    const int cap = t >> 4;          // capsule within warp

    // ---- staging maps ----
    const int xch = t & 1;           // x: 16B chunk within 32B row
    const int xr0 = (t >> 1) & 7;    // x: row base (rows xr0 + 8k)
    const int wch = t & 3;           // W: 16B chunk within 64B row
    const int wi0 = (t >> 2) & 3;    // W: i base (i = wi0 + 4m)

    const float* xg0 = x + ((size_t)xr0 * CC + c0 + cap) * IND + xch * 4;
    const float* wg0 = W + ((size_t)(c0 + cap) * IND + wi0) * OO + wch * 4;

    // ---- accumulators: 8 b-rows x 4 o-pairs (packed f32x2) ----
    uint64_t acc[8][4];
    #pragma unroll
    for (int k = 0; k < 8; ++k)
        #pragma unroll
        for (int j = 0; j < 4; ++j)
            acc[k][j] = 0ULL;

    // ---- stage helper (tile index jt into buffer bf) ----
    auto stage = [&](int bf, int jt) {
        float* dx = &sX[bf][cap * XCAP];
        const float* xg = xg0 + (size_t)jt * TI;
        #pragma unroll
        for (int k = 0; k < 8; ++k)
            cp16(&dx[xbase(xr0 + 8 * k) + xch * 4],
                 xg + (size_t)(8 * k) * CC * IND);
        float* dw = &sW[bf][cap * TI * OO];
        const float* wg = wg0 + (size_t)jt * TI * OO;
        #pragma unroll
        for (int m = 0; m < 2; ++m)
            cp16(&dw[(wi0 + 4 * m) * OO + wch * 4],
                 wg + (size_t)(4 * m) * OO);
        cp_commit();
    };

    // ---- prologue: fill 3 stages ----
    stage(0, 0);
    stage(1, 1);
    stage(2, 2);

    for (int j = 0; j < NTILES; ++j) {
        // wait until tile j's group has landed (outstanding groups: j..j+2)
        if (j <= NTILES - 3)      cp_wait2();
        else if (j == NTILES - 2) cp_wait1();
        else                      cp_wait0();
        __syncwarp();   // all lanes' tile-j data visible; all lanes done with j-1

        // refill the buffer that held tile j-1
        if (j + 3 < NTILES)
            stage((j + 3) & (PIPE - 1), j + 3);

        // ---- compute tile j ----
        const float* __restrict__ xb = &sX[j & (PIPE - 1)][cap * XCAP];
        const float* __restrict__ wb = &sW[j & (PIPE - 1)][cap * TI * OO];

        #pragma unroll
        for (int q = 0; q < 2; ++q) {          // two 4-i blocks
            float4 xv[8];
            #pragma unroll
            for (int k = 0; k < 8; ++k)
                xv[k] = *(const float4*)&xb[xbase(tb + 8 * k) + q * 4];

            #pragma unroll
            for (int r = 0; r < 4; ++r) {
                const int i = q * 4 + r;
                const ulonglong2 wA =
                    *(const ulonglong2*)&wb[i * OO + to * 8];
                const ulonglong2 wB =
                    *(const ulonglong2*)&wb[i * OO + to * 8 + 4];

                #pragma unroll
                for (int k = 0; k < 8; ++k) {
                    const float xs = (r == 0) ? xv[k].x :
                                     (r == 1) ? xv[k].y :
                                     (r == 2) ? xv[k].z : xv[k].w;
                    const uint64_t xd = pack_dup(xs);
                    fma2(acc[k][0], xd, wA.x);
                    fma2(acc[k][1], xd, wA.y);
                    fma2(acc[k][2], xd, wB.x);
                    fma2(acc[k][3], xd, wB.y);
                }
            }
        }
    }

    // ---- epilogue ----
    const int c  = c0 + cap;
    const int o0 = to * 8;
    const float4* bias4 = (const float4*)(bias + (size_t)c * OO + o0);
    const float4 bz0 = bias4[0];
    const float4 bz1 = bias4[1];

    #pragma unroll
    for (int k = 0; k < 8; ++k) {
        float v0, v1, v2, v3, v4, v5, v6, v7;
        unpack2(acc[k][0], v0, v1);
        unpack2(acc[k][1], v2, v3);
        unpack2(acc[k][2], v4, v5);
        unpack2(acc[k][3], v6, v7);

        float4 lo = make_float4(v0 + bz0.x, v1 + bz0.y, v2 + bz0.z, v3 + bz0.w);
        float4 hi = make_float4(v4 + bz1.x, v5 + bz1.y, v6 + bz1.z, v7 + bz1.w);

        const int b = tb + 8 * k;
        float* op = out + ((size_t)b * CC + c) * OO + o0;
        *(float4*)(op)     = lo;
        *(float4*)(op + 4) = hi;
    }
}

extern "C" void kernel_launch(void* const* d_in, const int* in_sizes, int n_in,
                              void* d_out, int out_size)
{
    (void)in_sizes; (void)n_in; (void)out_size;
    const float* x    = (const float*)d_in[0];
    const float* W    = (const float*)d_in[1];
    const float* bias = (const float*)d_in[2];
    float*       out  = (float*)d_out;

    primarycaps_kernel<<<CC / NCAP, NTH>>>(x, W, bias, out);
}

// round 7
// speedup vs baseline: 1.2724x; 1.0570x over previous
#include <cuda_runtime.h>
#include <cstdint>

#define BB 64
#define CC 4096
#define IND 512
#define OO 16
#define TI 16                 // i-tile
#define NTILES (IND / TI)     // 32
#define NCAP 2                // capsules per CTA (one warp)
#define NTH 32
#define PIPE 3

#define XCAP 1024             // 64 rows x 16 words per capsule per stage
#define WCAP 256              // 16 rows x 16 words per capsule per stage

// chunk swizzle: logical 16B chunk j of row r lives at position sigma(r,j)
__device__ __forceinline__ int sig(int r, int j) {
    return (j + ((r >> 1) & 3)) & 3;
}

// ---- packed f32x2 helpers ----
__device__ __forceinline__ uint64_t pack_dup(float x) {
    uint64_t r;
    asm("mov.b64 %0, {%1, %1};" : "=l"(r) : "f"(x));
    return r;
}
__device__ __forceinline__ void fma2(uint64_t& d, uint64_t a, uint64_t b) {
    asm("fma.rn.f32x2 %0, %1, %2, %0;" : "+l"(d) : "l"(a), "l"(b));
}
__device__ __forceinline__ void unpack2(uint64_t v, float& lo, float& hi) {
    asm("mov.b64 {%0, %1}, %2;" : "=f"(lo), "=f"(hi) : "l"(v));
}

// ---- cp.async 16B, L1-bypass ----
__device__ __forceinline__ void cp16(void* dst_smem, const void* src) {
    uint32_t d = (uint32_t)__cvta_generic_to_shared(dst_smem);
    asm volatile("cp.async.cg.shared.global [%0], [%1], 16;"
                 :: "r"(d), "l"(src) : "memory");
}
__device__ __forceinline__ void cp_commit() {
    asm volatile("cp.async.commit_group;" ::: "memory");
}
__device__ __forceinline__ void cp_wait2() {
    asm volatile("cp.async.wait_group 2;" ::: "memory");
}
__device__ __forceinline__ void cp_wait1() {
    asm volatile("cp.async.wait_group 1;" ::: "memory");
}
__device__ __forceinline__ void cp_wait0() {
    asm volatile("cp.async.wait_group 0;" ::: "memory");
}

__global__ __launch_bounds__(NTH, 7)
void primarycaps_kernel(const float* __restrict__ x,
                        const float* __restrict__ W,
                        const float* __restrict__ bias,
                        float* __restrict__ out)
{
    __shared__ float sX[PIPE][NCAP * XCAP];   // 3 x 8 KB
    __shared__ float sW[PIPE][NCAP * WCAP];   // 3 x 2 KB

    const int c0  = blockIdx.x * NCAP;
    const int t   = threadIdx.x;
    const int tb  = t & 7;           // compute: b-group, owns b = tb + 8k
    const int to  = (t >> 3) & 1;    // compute: o-half
    const int cap = t >> 4;          // compute: capsule within warp

    // staging map: lane -> (row base, 16B chunk); one instr = 8 rows x 4 chunks
    const int sr = (t >> 2) & 7;     // row base (rows sr + 8k)
    const int sj = t & 3;            // logical chunk 0..3

    // ---- accumulators: 8 b-rows x 4 o-pairs (packed f32x2) ----
    uint64_t acc[8][4];
    #pragma unroll
    for (int k = 0; k < 8; ++k)
        #pragma unroll
        for (int j = 0; j < 4; ++j)
            acc[k][j] = 0ULL;

    // ---- stage helper: tile jt into buffer bf ----
    auto stage = [&](int bf, int jt) {
        float* dx = sX[bf];
        // x: 16 cp16  (2 caps x 8 k), each warp-instr = 8 rows x 64B
        #pragma unroll
        for (int cc = 0; cc < NCAP; ++cc) {
            #pragma unroll
            for (int k = 0; k < 8; ++k) {
                const int row = sr + 8 * k;
                cp16(&dx[cc * XCAP + row * 16 + sig(row, sj) * 4],
                     x + ((size_t)row * CC + c0 + cc) * IND
                       + (size_t)jt * TI + sj * 4);
            }
        }
        // W: 4 cp16  (2 caps x 2 m)
        float* dw = sW[bf];
        #pragma unroll
        for (int cc = 0; cc < NCAP; ++cc) {
            #pragma unroll
            for (int m = 0; m < 2; ++m) {
                const int i = sr + 8 * m;   // sr in 0..7, i in 0..15
                cp16(&dw[cc * WCAP + i * 16 + sig(i, sj) * 4],
                     W + (((size_t)(c0 + cc)) * IND + (size_t)jt * TI + i) * OO
                       + sj * 4);
            }
        }
        cp_commit();
    };

    // ---- prologue: 2 stages in flight ----
    stage(0, 0);
    stage(1, 1);

    int bj = 0;                      // j % 3
    for (int j = 0; j < NTILES; ++j) {
        // issue stage j+2 (buffer (j+2)%3 == (j-1)%3, freed last iteration)
        if (j + 2 < NTILES) {
            int bs = bj + 2; if (bs >= PIPE) bs -= PIPE;
            stage(bs, j + 2);
        }
        // wait for tile j's group
        if (j < NTILES - 2)       cp_wait2();
        else if (j == NTILES - 2) cp_wait1();
        else                      cp_wait0();
        __syncwarp();

        // ---- compute tile j ----
        const float* __restrict__ xb = &sX[bj][cap * XCAP];
        const float* __restrict__ wb = &sW[bj][cap * WCAP];

        #pragma unroll
        for (int q = 0; q < 4; ++q) {           // 4-i blocks
            float4 xv[8];
            #pragma unroll
            for (int k = 0; k < 8; ++k) {
                const int row = tb + 8 * k;
                xv[k] = *(const float4*)&xb[row * 16 + sig(row, q) * 4];
            }

            #pragma unroll
            for (int r = 0; r < 4; ++r) {
                const int i = q * 4 + r;
                const ulonglong2 wA =
                    *(const ulonglong2*)&wb[i * 16 + sig(i, 2 * to) * 4];
                const ulonglong2 wB =
                    *(const ulonglong2*)&wb[i * 16 + sig(i, 2 * to + 1) * 4];

                #pragma unroll
                for (int k = 0; k < 8; ++k) {
                    const float xs = (r == 0) ? xv[k].x :
                                     (r == 1) ? xv[k].y :
                                     (r == 2) ? xv[k].z : xv[k].w;
                    const uint64_t xd = pack_dup(xs);
                    fma2(acc[k][0], xd, wA.x);
                    fma2(acc[k][1], xd, wA.y);
                    fma2(acc[k][2], xd, wB.x);
                    fma2(acc[k][3], xd, wB.y);
                }
            }
        }
        __syncwarp();   // all lanes done reading buffer bj before refill

        if (++bj >= PIPE) bj = 0;
    }

    // ---- epilogue ----
    const int c  = c0 + cap;
    const int o0 = to * 8;
    const float4* bias4 = (const float4*)(bias + (size_t)c * OO + o0);
    const float4 bz0 = bias4[0];
    const float4 bz1 = bias4[1];

    #pragma unroll
    for (int k = 0; k < 8; ++k) {
        float v0, v1, v2, v3, v4, v5, v6, v7;
        unpack2(acc[k][0], v0, v1);
        unpack2(acc[k][1], v2, v3);
        unpack2(acc[k][2], v4, v5);
        unpack2(acc[k][3], v6, v7);

        float4 lo = make_float4(v0 + bz0.x, v1 + bz0.y, v2 + bz0.z, v3 + bz0.w);
        float4 hi = make_float4(v4 + bz1.x, v5 + bz1.y, v6 + bz1.z, v7 + bz1.w);

        const int b = tb + 8 * k;
        float* op = out + ((size_t)b * CC + c) * OO + o0;
        *(float4*)(op)     = lo;
        *(float4*)(op + 4) = hi;
    }
}

extern "C" void kernel_launch(void* const* d_in, const int* in_sizes, int n_in,
                              void* d_out, int out_size)
{
    (void)in_sizes; (void)n_in; (void)out_size;
    const float* x    = (const float*)d_in[0];
    const float* W    = (const float*)d_in[1];
    const float* bias = (const float*)d_in[2];
    float*       out  = (float*)d_out;

    primarycaps_kernel<<<CC / NCAP, NTH>>>(x, W, bias, out);
}